// round 11
// baseline (speedup 1.0000x reference)
#include <cuda_runtime.h>
#include <cuda_bf16.h>
#include <math.h>

#define BATCHN 256
#define SEQN   512
#define IN_DIM 64
#define HID    256
#define NCTA   128
#define NTHR   512
#define LDXE   (SEQN * IN_DIM)

typedef __nv_bfloat16  bf16;
typedef __nv_bfloat162 bf162;

// ---------------- persistent device state (no allocation allowed) -----------
__device__ bf16  g_xhi[(size_t)BATCHN * SEQN * IN_DIM];
__device__ bf16  g_xlo[(size_t)BATCHN * SEQN * IN_DIM];
__device__ float g_h0f[2][BATCHN * HID];
__device__ bf16  g_h0hi[2][BATCHN * HID];
__device__ bf16  g_h0lo[2][BATCHN * HID];
__device__ float g_h1f[BATCHN * HID];
__device__ bf16  g_h1hi[BATCHN * HID];
__device__ bf16  g_h1lo[BATCHN * HID];
__device__ float g_z0[BATCHN * HID];
__device__ float g_z1[BATCHN * HID];
__device__ bf16  g_rh0hi[BATCHN * HID];
__device__ bf16  g_rh0lo[BATCHN * HID];
__device__ bf16  g_rh1hi[BATCHN * HID];
__device__ bf16  g_rh1lo[BATCHN * HID];

__device__ unsigned g_count = 0;
__device__ volatile unsigned g_gen = 0;

// ---------------------------- grid barrier ----------------------------------
__device__ __forceinline__ void grid_sync() {
    __syncthreads();
    if (threadIdx.x == 0) {
        __threadfence();
        unsigned gen = g_gen;
        unsigned a = atomicAdd(&g_count, 1u);
        if (a == NCTA - 1) {
            g_count = 0;
            __threadfence();
            g_gen = gen + 1;
        } else {
            while (g_gen == gen) { }
            __threadfence();
        }
    }
    __syncthreads();
}

// --------------------- shared memory layout (bf16 units) --------------------
#define WST 520             // W row stride (bank-stride 4 mod 32: conflict-free)
#define AST 136             // staged A row stride
#define A_TERM (64 * AST)
#define A_BUF  (2 * A_TERM)
#define OFF_WGH 0
#define OFF_WGL (32 * WST)
#define OFF_WCH (2 * 32 * WST)
#define OFF_WCL (OFF_WCH + 16 * WST)
#define OFF_A   (OFF_WCH + 2 * 16 * WST)
#define SMEM_ELEMS (OFF_A + 2 * A_BUF)
#define SMEM_BYTES (SMEM_ELEMS * 2)

__device__ __forceinline__ void cp16(void* dst_smem, const void* src_gmem) {
    unsigned u = (unsigned)__cvta_generic_to_shared(dst_smem);
    asm volatile("cp.async.cg.shared.global [%0], [%1], 16;"
                 :: "r"(u), "l"(src_gmem) : "memory");
}

struct Ck { const bf16* hi; const bf16* lo; int ld; int kw; };

// Stage one [64 x kw] hi+lo chunk into sA[buf].
__device__ __forceinline__ void stage_chunk(bf16* sm, int buf, const Ck c) {
    const int lg   = (c.kw == 128) ? 4 : 3;       // nseg = kw/8
    const int nseg = 1 << lg;
    const int tot  = 64 << lg;
    bf16* dh = sm + OFF_A + buf * A_BUF;
    bf16* dl = dh + A_TERM;
    for (int i = threadIdx.x; i < tot; i += NTHR) {
        int row = i >> lg, sg = i & (nseg - 1);
        int doff = row * AST + sg * 8;
        size_t soff = (size_t)row * c.ld + sg * 8;
        cp16(dh + doff, c.hi + soff);
        cp16(dl + doff, c.lo + soff);
    }
    asm volatile("cp.async.commit_group;" ::: "memory");
}

// ------------------------------- mma helper ---------------------------------
__device__ __forceinline__ void mma16816(float* c,
    unsigned a0, unsigned a1, unsigned a2, unsigned a3,
    unsigned b0, unsigned b1)
{
    asm("mma.sync.aligned.m16n8k16.row.col.f32.bf16.bf16.f32 "
        "{%0,%1,%2,%3}, {%4,%5,%6,%7}, {%8,%9}, {%0,%1,%2,%3};"
        : "+f"(c[0]), "+f"(c[1]), "+f"(c[2]), "+f"(c[3])
        : "r"(a0), "r"(a1), "r"(a2), "r"(a3), "r"(b0), "r"(b1));
}

// 3-term split MMA over KI k-iters of a staged chunk (A smem, W resident).
template<int KI>
__device__ __forceinline__ void mma_k(
    const bf16* sm, int buf, int wBase, int loDelta,
    int nloc, int kbase, int m0loc, int kstart, float (&acc)[4])
{
    const int lane = threadIdx.x & 31;
    const int g = lane >> 2, q = lane & 3;
    const bf16* aH = sm + OFF_A + buf * A_BUF + (m0loc + g) * AST + kstart + q * 2;
    const bf16* aL = aH + A_TERM;
    const bf16* bH = sm + wBase + (size_t)(nloc + g) * WST + kbase + kstart + q * 2;
    const bf16* bL = bH + loDelta;
#pragma unroll
    for (int kk = 0; kk < KI; kk++) {
        const int k = kk * 16;
        unsigned ah0 = *(const unsigned*)(aH + k);
        unsigned ah1 = *(const unsigned*)(aH + 8 * AST + k);
        unsigned ah2 = *(const unsigned*)(aH + k + 8);
        unsigned ah3 = *(const unsigned*)(aH + 8 * AST + k + 8);
        unsigned al0 = *(const unsigned*)(aL + k);
        unsigned al1 = *(const unsigned*)(aL + 8 * AST + k);
        unsigned al2 = *(const unsigned*)(aL + k + 8);
        unsigned al3 = *(const unsigned*)(aL + 8 * AST + k + 8);
        unsigned b0 = *(const unsigned*)(bH + k);
        unsigned b1 = *(const unsigned*)(bH + k + 8);
        unsigned c0 = *(const unsigned*)(bL + k);
        unsigned c1 = *(const unsigned*)(bL + k + 8);
        mma16816(acc, ah0, ah1, ah2, ah3, b0, b1);  // Ahi*Whi
        mma16816(acc, al0, al1, al2, al3, b0, b1);  // Alo*Whi
        mma16816(acc, ah0, ah1, ah2, ah3, c0, c1);  // Ahi*Wlo
    }
}

__device__ __forceinline__ void store_split2(bf16* hi, bf16* lo, int idx,
                                             float a, float b)
{
    bf16 ha = __float2bfloat16(a), hb = __float2bfloat16(b);
    bf16 la = __float2bfloat16(a - __bfloat162float(ha));
    bf16 lb = __float2bfloat16(b - __bfloat162float(hb));
    *(bf162*)&hi[idx] = __halves2bfloat162(ha, hb);
    *(bf162*)&lo[idx] = __halves2bfloat162(la, lb);
}

// ------------- gate tile: 64x32, 16 warps = 4m x 4n (n8 each) ---------------
__device__ __forceinline__ void run_gate(
    bf16* sm, int ctaM0, int n0base, const Ck* cks, int nc,
    const float* __restrict__ bias,
    float* zout, bf16* rhhi, bf16* rhlo, const float* __restrict__ hf)
{
    const int w = threadIdx.x >> 5;
    const int wm = w & 3, wn = w >> 2;
    float acc[4] = {};
    int kb = 0;
    for (int c = 0; c < nc; c++) {
        if (c == 0) stage_chunk(sm, 0, cks[0]);
        if (c + 1 < nc) {
            stage_chunk(sm, (c + 1) & 1, cks[c + 1]);
            asm volatile("cp.async.wait_group 1;" ::: "memory");
        } else {
            asm volatile("cp.async.wait_group 0;" ::: "memory");
        }
        __syncthreads();
        if (cks[c].kw == 128)
            mma_k<8>(sm, c & 1, OFF_WGH, OFF_WGL - OFF_WGH,
                     wn * 8, kb, wm * 16, 0, acc);
        else
            mma_k<4>(sm, c & 1, OFF_WGH, OFF_WGL - OFF_WGH,
                     wn * 8, kb, wm * 16, 0, acc);
        kb += cks[c].kw;
        __syncthreads();
    }

    const int lane = threadIdx.x & 31;
    const int g = lane >> 2, q = lane & 3;
    const bool isZ = (n0base < HID);
    const int n = n0base + wn * 8 + q * 2;
    float bx = bias[n], by = bias[n + 1];
#pragma unroll
    for (int h = 0; h < 2; h++) {
        int r = ctaM0 + wm * 16 + g + h * 8;
        float v0 = acc[h * 2 + 0] + bx;
        float v1 = acc[h * 2 + 1] + by;
        float s0 = 1.f / (1.f + __expf(-v0));
        float s1 = 1.f / (1.f + __expf(-v1));
        if (isZ) {
            *(float2*)&zout[r * HID + n] = make_float2(s0, s1);
        } else {
            int c = n - HID;
            float p0 = s0 * hf[r * HID + c];
            float p1 = s1 * hf[r * HID + c + 1];
            store_split2(rhhi, rhlo, r * HID + c, p0, p1);
        }
    }
}

// ---- cand tile: 64x16, 16 warps = 4m x 2n x 2k-half, smem reduction --------
__device__ __forceinline__ void run_cand(
    bf16* sm, int ctaM0, int n0base, const Ck* cks, int nc,
    const float* __restrict__ bias,
    const float* __restrict__ zin, const float* __restrict__ hof,
    float* houtf, bf16* houthi, bf16* houtlo)
{
    const int w = threadIdx.x >> 5;
    const int wm = w & 3, wn = (w >> 2) & 1, wk = w >> 3;
    const int lane = threadIdx.x & 31;
    float acc[4] = {};
    int kb = 0;
    for (int c = 0; c < nc; c++) {
        if (c == 0) stage_chunk(sm, 0, cks[0]);
        if (c + 1 < nc) {
            stage_chunk(sm, (c + 1) & 1, cks[c + 1]);
            asm volatile("cp.async.wait_group 1;" ::: "memory");
        } else {
            asm volatile("cp.async.wait_group 0;" ::: "memory");
        }
        __syncthreads();
        if (cks[c].kw == 128)
            mma_k<4>(sm, c & 1, OFF_WCH, OFF_WCL - OFF_WCH,
                     wn * 8, kb, wm * 16, wk * 64, acc);
        else
            mma_k<2>(sm, c & 1, OFF_WCH, OFF_WCL - OFF_WCH,
                     wn * 8, kb, wm * 16, wk * 32, acc);
        kb += cks[c].kw;
        __syncthreads();
    }

    // K-half reduction through smem scratch (A region is dead now).
    float* scr = (float*)(sm + OFF_A);
    const int si = ((wm * 2 + wn) * 32 + lane) * 4;
    if (wk == 1) {
        scr[si + 0] = acc[0]; scr[si + 1] = acc[1];
        scr[si + 2] = acc[2]; scr[si + 3] = acc[3];
    }
    __syncthreads();
    if (wk == 0) {
        acc[0] += scr[si + 0]; acc[1] += scr[si + 1];
        acc[2] += scr[si + 2]; acc[3] += scr[si + 3];

        const int g = lane >> 2, q = lane & 3;
        int n = n0base + wn * 8 + q * 2;
        float bx = bias[n], by = bias[n + 1];
#pragma unroll
        for (int h = 0; h < 2; h++) {
            int r = ctaM0 + wm * 16 + g + h * 8;
            float v0 = acc[h * 2 + 0] + bx;
            float v1 = acc[h * 2 + 1] + by;
            float t0 = tanhf(v0);
            float t1 = tanhf(v1);
            float2 z  = *(const float2*)&zin[r * HID + n];
            float2 ho = *(const float2*)&hof[r * HID + n];
            float h0n = (1.f - z.x) * ho.x + z.x * t0;
            float h1n = (1.f - z.y) * ho.y + z.y * t1;
            *(float2*)&houtf[r * HID + n] = make_float2(h0n, h1n);
            store_split2(houthi, houtlo, r * HID + n, h0n, h1n);
        }
    }
    __syncthreads();
}

// ----------------------- one-time weight preload ----------------------------
__device__ __forceinline__ void preload_wt(bf16* shi, bf16* slo,
                                           const float* __restrict__ W, int ldW,
                                           int n0, int NT, int K)
{
    for (int idx = threadIdx.x; idx < NT * K; idx += NTHR) {
        int n = idx % NT;
        int k = idx / NT;
        float v = W[(size_t)k * ldW + n0 + n];
        bf16 hi = __float2bfloat16(v);
        shi[(size_t)n * WST + k] = hi;
        slo[(size_t)n * WST + k] = __float2bfloat16(v - __bfloat162float(hi));
    }
}

// ---------------------------- persistent kernel -----------------------------
__global__ void __launch_bounds__(NTHR, 1)
rnn_kernel(const float* __restrict__ x,
           const float* __restrict__ Wz0, const float* __restrict__ bz0,
           const float* __restrict__ Wc0, const float* __restrict__ bc0,
           const float* __restrict__ Wz1, const float* __restrict__ bz1,
           const float* __restrict__ Wc1, const float* __restrict__ bc1,
           const float* __restrict__ gamma, const float* __restrict__ beta,
           float* __restrict__ out)
{
    extern __shared__ bf16 sm[];
    __shared__ float red[32];

    const int bid = blockIdx.x;
    const bool isG1 = (bid < 64);
    const int tA = bid & 63;
    const int tAM = tA >> 4, tAN = tA & 15;
    const int m0 = tAM * 64;

    // ---- init: sanitize + split x, zero states ----
    {
        int gtid = bid * NTHR + threadIdx.x;
        int gs = NCTA * NTHR;
        for (size_t i = gtid; i < (size_t)BATCHN * SEQN * IN_DIM; i += gs) {
            float v = x[i];
            if (v != v) v = 0.f;
            else if (isinf(v)) v = (v > 0.f) ? 10.f : -10.f;
            bf16 hi = __float2bfloat16(v);
            g_xhi[i] = hi;
            g_xlo[i] = __float2bfloat16(v - __bfloat162float(hi));
        }
        bf16 bz = __float2bfloat16(0.f);
        for (int i = gtid; i < BATCHN * HID; i += gs) {
            g_h0f[0][i] = 0.f; g_h0hi[0][i] = bz; g_h0lo[0][i] = bz;
            g_h1f[i] = 0.f;    g_h1hi[i] = bz;    g_h1lo[i] = bz;
        }
    }

    // ---- resident weight preload ----
    if (isG1) {
        preload_wt(sm + OFF_WGH, sm + OFF_WGL, Wz1, 3 * HID, tAN * 32, 32, 2 * HID);
        preload_wt(sm + OFF_WCH, sm + OFF_WCL, Wc1, HID,     tAN * 16, 16, 2 * HID);
    } else {
        preload_wt(sm + OFF_WGH, sm + OFF_WGL, Wz0, 3 * HID, tAN * 32, 32, HID + IN_DIM);
        preload_wt(sm + OFF_WCH, sm + OFF_WCL, Wc0, HID,     tAN * 16, 16, HID + IN_DIM);
    }
    grid_sync();

    // ---- pipelined recurrence ----
    for (int st = 0; st <= SEQN; ++st) {
        const float* h0f  = g_h0f[st & 1];
        const bf16*  h0hi = g_h0hi[st & 1];
        const bf16*  h0lo = g_h0lo[st & 1];
        float* h0fN  = g_h0f[(st + 1) & 1];
        bf16*  h0hiN = g_h0hi[(st + 1) & 1];
        bf16*  h0loN = g_h0lo[(st + 1) & 1];
        const bf16* xthi = g_xhi + (size_t)st * IN_DIM;
        const bf16* xtlo = g_xlo + (size_t)st * IN_DIM;

        // phase A: gates0(st) on G0 || gates1(st-1) on G1
        if (isG1) {
            if (st > 0) {
                Ck cks[4] = {
                    {g_h1hi + m0 * HID,       g_h1lo + m0 * HID,       HID, 128},
                    {g_h1hi + m0 * HID + 128, g_h1lo + m0 * HID + 128, HID, 128},
                    {h0hi  + m0 * HID,        h0lo  + m0 * HID,        HID, 128},
                    {h0hi  + m0 * HID + 128,  h0lo  + m0 * HID + 128,  HID, 128}};
                run_gate(sm, m0, tAN * 32, cks, 4, bz1,
                         g_z1, g_rh1hi, g_rh1lo, g_h1f);
            }
        } else {
            if (st < SEQN) {
                Ck cks[3] = {
                    {h0hi + m0 * HID,        h0lo + m0 * HID,        HID, 128},
                    {h0hi + m0 * HID + 128,  h0lo + m0 * HID + 128,  HID, 128},
                    {xthi + (size_t)m0 * LDXE, xtlo + (size_t)m0 * LDXE, LDXE, 64}};
                run_gate(sm, m0, tAN * 32, cks, 3, bz0,
                         g_z0, g_rh0hi, g_rh0lo, h0f);
            }
        }
        grid_sync();

        // phase B: cand0(st) on G0 || cand1(st-1) on G1
        if (isG1) {
            if (st > 0) {
                Ck cks[4] = {
                    {g_rh1hi + m0 * HID,       g_rh1lo + m0 * HID,       HID, 128},
                    {g_rh1hi + m0 * HID + 128, g_rh1lo + m0 * HID + 128, HID, 128},
                    {h0hi   + m0 * HID,        h0lo   + m0 * HID,        HID, 128},
                    {h0hi   + m0 * HID + 128,  h0lo   + m0 * HID + 128,  HID, 128}};
                run_cand(sm, m0, tAN * 16, cks, 4, bc1,
                         g_z1, g_h1f, g_h1f, g_h1hi, g_h1lo);
            }
        } else {
            if (st < SEQN) {
                Ck cks[3] = {
                    {g_rh0hi + m0 * HID,       g_rh0lo + m0 * HID,       HID, 128},
                    {g_rh0hi + m0 * HID + 128, g_rh0lo + m0 * HID + 128, HID, 128},
                    {xthi + (size_t)m0 * LDXE, xtlo + (size_t)m0 * LDXE, LDXE, 64}};
                run_cand(sm, m0, tAN * 16, cks, 3, bc0,
                         g_z0, h0f, h0fN, h0hiN, h0loN);
            }
        }
        grid_sync();
    }

    // ---- LayerNorm on final h1 ----
    {
        const int tid = threadIdx.x;
        const int wid = tid >> 5, lane = tid & 31;
        const bool valid = (tid < HID);
        for (int b = bid; b < BATCHN; b += NCTA) {
            float v = valid ? g_h1f[b * HID + tid] : 0.f;
            float sum = v, sq = v * v;
#pragma unroll
            for (int off = 16; off; off >>= 1) {
                sum += __shfl_xor_sync(0xFFFFFFFFu, sum, off);
                sq  += __shfl_xor_sync(0xFFFFFFFFu, sq,  off);
            }
            if (lane == 0) { red[wid] = sum; red[16 + wid] = sq; }
            __syncthreads();
            float ts = 0.f, tq = 0.f;
#pragma unroll
            for (int w = 0; w < 8; w++) { ts += red[w]; tq += red[16 + w]; }
            float mean = ts * (1.f / HID);
            float var  = tq * (1.f / HID) - mean * mean;
            float rstd = rsqrtf(var + 1e-5f);
            if (valid)
                out[b * HID + tid] = (v - mean) * rstd * gamma[tid] + beta[tid];
            __syncthreads();
        }
    }
}

extern "C" void kernel_launch(void* const* d_in, const int* in_sizes, int n_in,
                              void* d_out, int out_size) {
    (void)in_sizes; (void)n_in; (void)out_size;
    const float* x     = (const float*)d_in[0];
    const float* Wz0   = (const float*)d_in[1];
    const float* bz0   = (const float*)d_in[2];
    const float* Wc0   = (const float*)d_in[3];
    const float* bc0   = (const float*)d_in[4];
    const float* Wz1   = (const float*)d_in[5];
    const float* bz1   = (const float*)d_in[6];
    const float* Wc1   = (const float*)d_in[7];
    const float* bc1   = (const float*)d_in[8];
    const float* gamma = (const float*)d_in[9];
    const float* beta  = (const float*)d_in[10];
    float* out = (float*)d_out;

    cudaFuncSetAttribute(rnn_kernel,
                         cudaFuncAttributeMaxDynamicSharedMemorySize, SMEM_BYTES);
    rnn_kernel<<<NCTA, NTHR, SMEM_BYTES>>>(x, Wz0, bz0, Wc0, bc0,
                                           Wz1, bz1, Wc1, bc1, gamma, beta, out);
}